// round 1
// baseline (speedup 1.0000x reference)
#include <cuda_runtime.h>

// GroupQuerySelfAttention: B=2, S=2048, D=768, NH=12, GH=4 (GQA rep=3), HD=64
// Faithful quirks: MASK_FILL = -1e-9 (softmax over ALL keys, masked scores ~0),
// and the buggy output merge == attention output stored [B, NH, HD, S].

namespace {
constexpr int kB  = 2;
constexpr int kS  = 2048;
constexpr int kD  = 768;
constexpr int kNH = 12;
constexpr int kGH = 4;
constexpr int kHD = 64;
constexpr int kREP = 3;
constexpr float kScale = 0.125f;      // 64^-0.5
constexpr float kMaskFill = -1e-9f;   // faithful to reference (NOT -1e9)
}

// Scratch (no cudaMalloc allowed): ~33 MB total
__device__ float g_Q[(size_t)kB * kNH * kS * kHD];   // [b, h, s, hd]
__device__ float g_K[(size_t)kB * kGH * kS * kHD];   // [b, g, s, hd]
__device__ float g_V[(size_t)kB * kGH * kS * kHD];   // [b, g, s, hd]
__device__ float g_O[(size_t)kB * kNH * kHD * kS];   // [b, h, hd, q]  (pre-transposed!)

// ---------------------------------------------------------------------------
// Tiled GEMM: C[4096 x N] = A[4096 x 768] @ W[768 x N] + bias
// Output scattered to head-major layout: out[((b*heads + h)*S + s)*hd + c%hd]
// (heads=1, hd=768 => plain row-major). BM=BN=64, BK=16, 256 thr, 4x4 microtile.
// ---------------------------------------------------------------------------
__global__ __launch_bounds__(256) void gemm_proj(
    const float* __restrict__ A, const float* __restrict__ W,
    const float* __restrict__ bias, float* __restrict__ out,
    int N, int heads, int hd)
{
    __shared__ float As[16][65];     // [k][m], padded
    __shared__ float Bs[16 * 64];    // [k][n]

    const int tid = threadIdx.x;
    const int tx = tid & 15;         // n-group
    const int ty = tid >> 4;         // m-group
    const int rowBase = blockIdx.y * 64;
    const int colBase = blockIdx.x * 64;

    const int arow = tid >> 2;             // 0..63
    const int akq  = (tid & 3) * 4;        // 0,4,8,12
    const int bkk  = tid >> 4;             // 0..15
    const int bcq  = (tid & 15) * 4;       // 0..60

    float acc[4][4] = {};

    for (int k0 = 0; k0 < kD; k0 += 16) {
        float4 av = *reinterpret_cast<const float4*>(
            A + (size_t)(rowBase + arow) * kD + k0 + akq);
        float4 bv = *reinterpret_cast<const float4*>(
            W + (size_t)(k0 + bkk) * N + colBase + bcq);
        __syncthreads();
        As[akq + 0][arow] = av.x;
        As[akq + 1][arow] = av.y;
        As[akq + 2][arow] = av.z;
        As[akq + 3][arow] = av.w;
        *reinterpret_cast<float4*>(Bs + bkk * 64 + bcq) = bv;
        __syncthreads();

        #pragma unroll
        for (int k = 0; k < 16; ++k) {
            float a[4];
            #pragma unroll
            for (int i = 0; i < 4; ++i) a[i] = As[k][ty * 4 + i];
            float4 b4 = *reinterpret_cast<const float4*>(Bs + k * 64 + tx * 4);
            float b[4] = {b4.x, b4.y, b4.z, b4.w};
            #pragma unroll
            for (int i = 0; i < 4; ++i)
                #pragma unroll
                for (int j = 0; j < 4; ++j)
                    acc[i][j] += a[i] * b[j];
        }
    }

    #pragma unroll
    for (int i = 0; i < 4; ++i) {
        const int r = rowBase + ty * 4 + i;
        const int bb = r / kS;
        const int s = r - bb * kS;
        #pragma unroll
        for (int j = 0; j < 4; ++j) {
            const int c = colBase + tx * 4 + j;
            const int h = c / hd;
            const int cc = c - h * hd;
            out[((size_t)(bb * heads + h) * kS + s) * hd + cc] = acc[i][j] + bias[c];
        }
    }
}

// ---------------------------------------------------------------------------
// Fused attention, flash-style online softmax. One block = 64 queries of one
// (b, h). Streams all 32 key tiles (NO skipping: mask fill is -1e-9, not -inf).
// Output written transposed: g_O[b, h, hd, q]  => final GEMM input is row-major.
// Dynamic smem: Qs[64*65] + Ks[64*65] (reused for P) + Vs[64*64] = 49664 B.
// ---------------------------------------------------------------------------
__global__ __launch_bounds__(256) void attn_kernel()
{
    extern __shared__ float sm[];
    float* Qs = sm;                    // stride 65
    float* Ks = sm + 64 * 65;          // stride 65, reused as P after QK^T
    float* Vs = sm + 2 * 64 * 65;      // stride 64

    const int qt = blockIdx.x;         // 0..31
    const int h  = blockIdx.y;         // 0..11
    const int b  = blockIdx.z;         // 0..1
    const int g  = h / kREP;

    const float* Qp = g_Q + (size_t)(b * kNH + h) * kS * kHD;
    const float* Kp = g_K + (size_t)(b * kGH + g) * kS * kHD;
    const float* Vp = g_V + (size_t)(b * kGH + g) * kS * kHD;

    const int tid = threadIdx.x;
    const int tx = tid & 15;           // key / hd group
    const int ty = tid >> 4;           // query group

    // Load Q tile [64 x 64]
    #pragma unroll
    for (int r = 0; r < 4; ++r) {
        const int idx = tid + 256 * r;
        const int row = idx >> 4;
        const int d4  = (idx & 15) * 4;
        float4 v = *reinterpret_cast<const float4*>(Qp + (size_t)(qt * 64 + row) * kHD + d4);
        Qs[row * 65 + d4 + 0] = v.x;
        Qs[row * 65 + d4 + 1] = v.y;
        Qs[row * 65 + d4 + 2] = v.z;
        Qs[row * 65 + d4 + 3] = v.w;
    }

    float m[4], l[4], acc[4][4];
    #pragma unroll
    for (int i = 0; i < 4; ++i) {
        m[i] = -1e30f;
        l[i] = 0.f;
        #pragma unroll
        for (int j = 0; j < 4; ++j) acc[i][j] = 0.f;
    }

    const int q0 = qt * 64 + ty * 4;

    for (int kt = 0; kt < kS / 64; ++kt) {
        __syncthreads();  // previous PV reads of Ks/Vs complete
        #pragma unroll
        for (int r = 0; r < 4; ++r) {
            const int idx = tid + 256 * r;
            const int row = idx >> 4;
            const int d4  = (idx & 15) * 4;
            float4 kv = *reinterpret_cast<const float4*>(Kp + (size_t)(kt * 64 + row) * kHD + d4);
            Ks[row * 65 + d4 + 0] = kv.x;
            Ks[row * 65 + d4 + 1] = kv.y;
            Ks[row * 65 + d4 + 2] = kv.z;
            Ks[row * 65 + d4 + 3] = kv.w;
            float4 vv = *reinterpret_cast<const float4*>(Vp + (size_t)(kt * 64 + row) * kHD + d4);
            *reinterpret_cast<float4*>(Vs + row * 64 + d4) = vv;
        }
        __syncthreads();

        // S = Q @ K^T (4x4 per thread)
        float sv[4][4] = {};
        #pragma unroll 8
        for (int d = 0; d < 64; ++d) {
            float a[4], kb[4];
            #pragma unroll
            for (int i = 0; i < 4; ++i) a[i]  = Qs[(ty * 4 + i) * 65 + d];
            #pragma unroll
            for (int j = 0; j < 4; ++j) kb[j] = Ks[(tx * 4 + j) * 65 + d];
            #pragma unroll
            for (int i = 0; i < 4; ++i)
                #pragma unroll
                for (int j = 0; j < 4; ++j)
                    sv[i][j] += a[i] * kb[j];
        }

        // scale + mask + online softmax update
        const int k0 = kt * 64 + tx * 4;
        float p[4][4];
        float alpha[4];
        #pragma unroll
        for (int i = 0; i < 4; ++i) {
            float tmax = -1e30f;
            #pragma unroll
            for (int j = 0; j < 4; ++j) {
                float s = (k0 + j <= q0 + i) ? sv[i][j] * kScale : kMaskFill;
                sv[i][j] = s;
                tmax = fmaxf(tmax, s);
            }
            #pragma unroll
            for (int off = 8; off >= 1; off >>= 1)
                tmax = fmaxf(tmax, __shfl_xor_sync(0xffffffffu, tmax, off));
            const float mnew = fmaxf(m[i], tmax);
            alpha[i] = __expf(m[i] - mnew);
            float rsum = 0.f;
            #pragma unroll
            for (int j = 0; j < 4; ++j) {
                p[i][j] = __expf(sv[i][j] - mnew);
                rsum += p[i][j];
            }
            #pragma unroll
            for (int off = 8; off >= 1; off >>= 1)
                rsum += __shfl_xor_sync(0xffffffffu, rsum, off);
            l[i] = l[i] * alpha[i] + rsum;
            m[i] = mnew;
        }

        __syncthreads();  // all QK^T reads of Ks done before overwrite with P
        #pragma unroll
        for (int i = 0; i < 4; ++i)
            #pragma unroll
            for (int j = 0; j < 4; ++j)
                Ks[(ty * 4 + i) * 65 + tx * 4 + j] = p[i][j];
        __syncthreads();

        #pragma unroll
        for (int i = 0; i < 4; ++i)
            #pragma unroll
            for (int j = 0; j < 4; ++j)
                acc[i][j] *= alpha[i];

        // O += P @ V
        #pragma unroll 8
        for (int kk = 0; kk < 64; ++kk) {
            float pr[4];
            #pragma unroll
            for (int i = 0; i < 4; ++i) pr[i] = Ks[(ty * 4 + i) * 65 + kk];
            float4 v4 = *reinterpret_cast<const float4*>(Vs + kk * 64 + tx * 4);
            #pragma unroll
            for (int i = 0; i < 4; ++i) {
                acc[i][0] += pr[i] * v4.x;
                acc[i][1] += pr[i] * v4.y;
                acc[i][2] += pr[i] * v4.z;
                acc[i][3] += pr[i] * v4.w;
            }
        }
    }

    // Write transposed: g_O[b, h, hd, q]
    #pragma unroll
    for (int i = 0; i < 4; ++i) {
        const float inv = 1.f / l[i];
        const int q = qt * 64 + ty * 4 + i;
        #pragma unroll
        for (int j = 0; j < 4; ++j) {
            const int hd = tx * 4 + j;
            g_O[((size_t)(b * kNH + h) * kHD + hd) * kS + q] = acc[i][j] * inv;
        }
    }
}

extern "C" void kernel_launch(void* const* d_in, const int* in_sizes, int n_in,
                              void* d_out, int out_size)
{
    (void)in_sizes; (void)n_in; (void)out_size;
    const float* x  = (const float*)d_in[0];
    // d_in[1] = masks (tril, known analytically — unused)
    const float* Wq = (const float*)d_in[2];
    const float* bq = (const float*)d_in[3];
    const float* Wk = (const float*)d_in[4];
    const float* bk = (const float*)d_in[5];
    const float* Wv = (const float*)d_in[6];
    const float* bv = (const float*)d_in[7];
    const float* Wo = (const float*)d_in[8];
    const float* bo = (const float*)d_in[9];
    float* out = (float*)d_out;

    void *qp, *kp, *vp, *op;
    cudaGetSymbolAddress(&qp, g_Q);
    cudaGetSymbolAddress(&kp, g_K);
    cudaGetSymbolAddress(&vp, g_V);
    cudaGetSymbolAddress(&op, g_O);

    const int smem_attn = (2 * 64 * 65 + 64 * 64) * (int)sizeof(float);  // 49664
    cudaFuncSetAttribute(attn_kernel, cudaFuncAttributeMaxDynamicSharedMemorySize, smem_attn);

    // QKV projections into head-major scratch
    gemm_proj<<<dim3(kD / 64, (kB * kS) / 64), 256>>>(x, Wq, bq, (float*)qp, kD, kNH, kHD);
    gemm_proj<<<dim3((kGH * kHD) / 64, (kB * kS) / 64), 256>>>(x, Wk, bk, (float*)kp, kGH * kHD, kGH, kHD);
    gemm_proj<<<dim3((kGH * kHD) / 64, (kB * kS) / 64), 256>>>(x, Wv, bv, (float*)vp, kGH * kHD, kGH, kHD);

    // Fused attention (writes [b, h, hd, q] — the buggy merge for free)
    attn_kernel<<<dim3(kS / 64, kNH, kB), 256, smem_attn>>>();

    // Final projection: g_O viewed as [4096 x 768] row-major @ Wo + bo
    gemm_proj<<<dim3(kD / 64, (kB * kS) / 64), 256>>>((const float*)op, Wo, bo, out, kD, 1, kD);
}

// round 4
// speedup vs baseline: 1.7571x; 1.7571x over previous
#include <cuda_runtime.h>
#include <cuda_fp16.h>
#include <cstdint>

// GroupQuerySelfAttention: B=2, S=2048, D=768, NH=12, GH=4 (rep=3), HD=64
// MASK_FILL = -1e-9 => masked P entries == exp(-1e-9) == 1.0f; softmax needs
// no max subtraction (scores bounded). Attention via mma.sync (tf32 QK^T with
// rna-rounded operands, fp16 PV). Buggy merge == attention out as [B,NH,HD,S].

namespace {
constexpr int kB  = 2;
constexpr int kS  = 2048;
constexpr int kD  = 768;
constexpr int kNH = 12;
constexpr int kGH = 4;
constexpr int kHD = 64;
constexpr int kREP = 3;
constexpr float kScale = 0.125f;
}

__device__ float g_Q[(size_t)kB * kNH * kS * kHD];   // [b, h, s, hd]
__device__ float g_K[(size_t)kB * kGH * kS * kHD];   // [b, g, s, hd]
__device__ float g_V[(size_t)kB * kGH * kS * kHD];   // [b, g, s, hd]
__device__ float g_O[(size_t)kB * kNH * kHD * kS];   // [b, h, hd, q]

// ---------------------------------------------------------------------------
// mma.sync helpers (baseline PTX — compute_103-family safe)
// ---------------------------------------------------------------------------
__device__ __forceinline__ void mma_tf32(float* d, const uint32_t* a,
                                         uint32_t b0, uint32_t b1) {
    asm volatile(
        "mma.sync.aligned.m16n8k8.row.col.f32.tf32.tf32.f32 "
        "{%0,%1,%2,%3}, {%4,%5,%6,%7}, {%8,%9}, {%0,%1,%2,%3};"
        : "+f"(d[0]), "+f"(d[1]), "+f"(d[2]), "+f"(d[3])
        : "r"(a[0]), "r"(a[1]), "r"(a[2]), "r"(a[3]), "r"(b0), "r"(b1));
}
__device__ __forceinline__ void mma_f16(float* d, const uint32_t* a,
                                        uint32_t b0, uint32_t b1) {
    asm volatile(
        "mma.sync.aligned.m16n8k16.row.col.f32.f16.f16.f32 "
        "{%0,%1,%2,%3}, {%4,%5,%6,%7}, {%8,%9}, {%0,%1,%2,%3};"
        : "+f"(d[0]), "+f"(d[1]), "+f"(d[2]), "+f"(d[3])
        : "r"(a[0]), "r"(a[1]), "r"(a[2]), "r"(a[3]), "r"(b0), "r"(b1));
}
__device__ __forceinline__ uint32_t pack_f16(float lo, float hi) {
    uint32_t r;
    asm("cvt.rn.f16x2.f32 %0, %1, %2;" : "=r"(r) : "f"(hi), "f"(lo));
    return r;
}
__device__ __forceinline__ float rna_tf32(float f) {
    uint32_t r;
    asm("cvt.rna.tf32.f32 %0, %1;" : "=r"(r) : "f"(f));
    return __uint_as_float(r);
}

// ---------------------------------------------------------------------------
// SIMT projection GEMM (proven in R1)
// ---------------------------------------------------------------------------
__global__ __launch_bounds__(256) void gemm_proj(
    const float* __restrict__ A, const float* __restrict__ W,
    const float* __restrict__ bias, float* __restrict__ out,
    int N, int heads, int hd)
{
    __shared__ float As[16][65];
    __shared__ float Bs[16 * 64];
    const int tid = threadIdx.x;
    const int tx = tid & 15, ty = tid >> 4;
    const int rowBase = blockIdx.y * 64, colBase = blockIdx.x * 64;
    const int arow = tid >> 2, akq = (tid & 3) * 4;
    const int bkk = tid >> 4, bcq = (tid & 15) * 4;
    float acc[4][4] = {};
    for (int k0 = 0; k0 < kD; k0 += 16) {
        float4 av = *reinterpret_cast<const float4*>(A + (size_t)(rowBase + arow) * kD + k0 + akq);
        float4 bv = *reinterpret_cast<const float4*>(W + (size_t)(k0 + bkk) * N + colBase + bcq);
        __syncthreads();
        As[akq + 0][arow] = av.x; As[akq + 1][arow] = av.y;
        As[akq + 2][arow] = av.z; As[akq + 3][arow] = av.w;
        *reinterpret_cast<float4*>(Bs + bkk * 64 + bcq) = bv;
        __syncthreads();
        #pragma unroll
        for (int k = 0; k < 16; ++k) {
            float a[4];
            #pragma unroll
            for (int i = 0; i < 4; ++i) a[i] = As[k][ty * 4 + i];
            float4 b4 = *reinterpret_cast<const float4*>(Bs + k * 64 + tx * 4);
            float b[4] = {b4.x, b4.y, b4.z, b4.w};
            #pragma unroll
            for (int i = 0; i < 4; ++i)
                #pragma unroll
                for (int j = 0; j < 4; ++j)
                    acc[i][j] += a[i] * b[j];
        }
    }
    #pragma unroll
    for (int i = 0; i < 4; ++i) {
        const int r = rowBase + ty * 4 + i;
        const int bb = r / kS, s = r - bb * kS;
        #pragma unroll
        for (int j = 0; j < 4; ++j) {
            const int c = colBase + tx * 4 + j;
            const int h = c / hd, cc = c - h * hd;
            out[((size_t)(bb * heads + h) * kS + s) * hd + cc] = acc[i][j] + bias[c];
        }
    }
}

// ---------------------------------------------------------------------------
// Tensor-core attention (mma.sync). CTA = 128 queries of one (b,h), 8 warps,
// warp = 16 q rows. 64-key tiles in two 32-key halves (regs <= 128, 2 CTA/SM).
// QK^T: tf32 m16n8k8, operands rna-rounded at staging. Softmax exact (no max:
// masked p == 1.0f). PV: fp16 m16n8k16, A = repacked S C-frags (FA-2 identity).
// Smem: Qs[128][68]f32 + Ks[64][68]f32 + Vt[64][72]f16 = 61440 B.
// ---------------------------------------------------------------------------
namespace {
constexpr int QS_STRIDE = 68;
constexpr int VT_STRIDE = 72;
constexpr int SMEM_ATTN = 128 * 68 * 4 + 64 * 68 * 4 + 64 * 72 * 2;  // 61440
}

__global__ __launch_bounds__(256, 2) void attn_mma()
{
    extern __shared__ char smem[];
    float* Qs = reinterpret_cast<float*>(smem);                  // [128][68]
    float* Ks = Qs + 128 * QS_STRIDE;                            // [64][68]
    __half* Vt = reinterpret_cast<__half*>(Ks + 64 * QS_STRIDE); // [64][72]

    const int tid = threadIdx.x;
    const int lane = tid & 31;
    const int w = tid >> 5;
    const int qt = blockIdx.x, h = blockIdx.y, b = blockIdx.z;
    const int g = h / kREP;
    const int lr = lane >> 2;        // fragment row 0..7
    const int lc = lane & 3;         // fragment col group 0..3

    const float* Qp = g_Q + ((size_t)(b * kNH + h) * kS + (size_t)qt * 128) * kHD;
    const float* Kp = g_K + (size_t)(b * kGH + g) * kS * kHD;
    const float* Vp = g_V + (size_t)(b * kGH + g) * kS * kHD;

    // stage Q [128 x 64], rna-rounded to tf32
    for (int i = tid; i < 128 * 16; i += 256) {
        const int r = i >> 4, c4 = (i & 15) * 4;
        float4 v = *reinterpret_cast<const float4*>(Qp + (size_t)r * kHD + c4);
        float* dst = Qs + r * QS_STRIDE + c4;
        dst[0] = rna_tf32(v.x); dst[1] = rna_tf32(v.y);
        dst[2] = rna_tf32(v.z); dst[3] = rna_tf32(v.w);
    }
    __syncthreads();

    // Q fragments (tf32 m16n8k8 A), hoisted: 8 k-steps x 4 regs
    uint32_t qa[8][4];
    {
        const int r0 = w * 16 + lr;
        #pragma unroll
        for (int ks = 0; ks < 8; ++ks) {
            qa[ks][0] = __float_as_uint(Qs[r0 * QS_STRIDE + ks * 8 + lc]);
            qa[ks][1] = __float_as_uint(Qs[(r0 + 8) * QS_STRIDE + ks * 8 + lc]);
            qa[ks][2] = __float_as_uint(Qs[r0 * QS_STRIDE + ks * 8 + lc + 4]);
            qa[ks][3] = __float_as_uint(Qs[(r0 + 8) * QS_STRIDE + ks * 8 + lc + 4]);
        }
    }

    float oacc[8][4];
    #pragma unroll
    for (int i = 0; i < 8; ++i)
        #pragma unroll
        for (int j = 0; j < 4; ++j) oacc[i][j] = 0.f;
    float lsum0 = 0.f, lsum1 = 0.f;
    const int q0 = qt * 128 + w * 16 + lr;   // global q row (and q0+8)

    for (int kt = 0; kt < kS / 64; ++kt) {
        __syncthreads();
        const float* Kt  = Kp + (size_t)kt * 64 * kHD;
        const float* Vtg = Vp + (size_t)kt * 64 * kHD;
        for (int i = tid; i < 64 * 16; i += 256) {
            const int r = i >> 4, c4 = (i & 15) * 4;
            float4 v = *reinterpret_cast<const float4*>(Kt + (size_t)r * kHD + c4);
            float* dst = Ks + r * QS_STRIDE + c4;
            dst[0] = rna_tf32(v.x); dst[1] = rna_tf32(v.y);
            dst[2] = rna_tf32(v.z); dst[3] = rna_tf32(v.w);
        }
        for (int i = tid; i < 64 * 16; i += 256) {
            const int r = i >> 4, c4 = (i & 15) * 4;   // r = key, c4 = hd base
            float4 v = *reinterpret_cast<const float4*>(Vtg + (size_t)r * kHD + c4);
            Vt[(c4 + 0) * VT_STRIDE + r] = __float2half_rn(v.x);
            Vt[(c4 + 1) * VT_STRIDE + r] = __float2half_rn(v.y);
            Vt[(c4 + 2) * VT_STRIDE + r] = __float2half_rn(v.z);
            Vt[(c4 + 3) * VT_STRIDE + r] = __float2half_rn(v.w);
        }
        __syncthreads();

        #pragma unroll
        for (int sub = 0; sub < 2; ++sub) {
            // S (16 x 32) = Q @ K^T, tf32
            float sacc[4][4];
            #pragma unroll
            for (int i = 0; i < 4; ++i)
                #pragma unroll
                for (int j = 0; j < 4; ++j) sacc[i][j] = 0.f;

            #pragma unroll
            for (int nf = 0; nf < 4; ++nf) {
                const int key = sub * 32 + nf * 8 + lr;
                const float* krow = Ks + key * QS_STRIDE;
                #pragma unroll
                for (int ks = 0; ks < 8; ++ks) {
                    const uint32_t b0 = __float_as_uint(krow[ks * 8 + lc]);
                    const uint32_t b1 = __float_as_uint(krow[ks * 8 + lc + 4]);
                    mma_tf32(sacc[nf], qa[ks], b0, b1);
                }
            }

            // softmax (exact, no max) + repack to fp16 PV A-fragments
            uint32_t pa[2][4];
            #pragma unroll
            for (int nf = 0; nf < 4; ++nf) {
                const int colb = kt * 64 + sub * 32 + nf * 8 + 2 * lc;
                const float p0 = (colb     <= q0)     ? __expf(sacc[nf][0] * kScale) : 1.0f;
                const float p1 = (colb + 1 <= q0)     ? __expf(sacc[nf][1] * kScale) : 1.0f;
                const float p2 = (colb     <= q0 + 8) ? __expf(sacc[nf][2] * kScale) : 1.0f;
                const float p3 = (colb + 1 <= q0 + 8) ? __expf(sacc[nf][3] * kScale) : 1.0f;
                lsum0 += p0 + p1;
                lsum1 += p2 + p3;
                const int kk = nf >> 1;
                if ((nf & 1) == 0) {
                    pa[kk][0] = pack_f16(p0, p1);
                    pa[kk][1] = pack_f16(p2, p3);
                } else {
                    pa[kk][2] = pack_f16(p0, p1);
                    pa[kk][3] = pack_f16(p2, p3);
                }
            }

            // O (16 x 64) += P @ V, fp16
            #pragma unroll
            for (int nd = 0; nd < 8; ++nd) {
                const __half* vrow = Vt + (nd * 8 + lr) * VT_STRIDE + sub * 32;
                #pragma unroll
                for (int kk = 0; kk < 2; ++kk) {
                    const uint32_t b0 = *reinterpret_cast<const uint32_t*>(vrow + kk * 16 + 2 * lc);
                    const uint32_t b1 = *reinterpret_cast<const uint32_t*>(vrow + kk * 16 + 2 * lc + 8);
                    mma_f16(oacc[nd], pa[kk], b0, b1);
                }
            }
        }
    }

    // reduce row sums across the quad (lanes sharing lr)
    lsum0 += __shfl_xor_sync(0xffffffffu, lsum0, 1);
    lsum0 += __shfl_xor_sync(0xffffffffu, lsum0, 2);
    lsum1 += __shfl_xor_sync(0xffffffffu, lsum1, 1);
    lsum1 += __shfl_xor_sync(0xffffffffu, lsum1, 2);
    const float inv0 = 1.f / lsum0;
    const float inv1 = 1.f / lsum1;

    // write O transposed: g_O[b, h, hd, q]
    float* Op = g_O + (size_t)(b * kNH + h) * kHD * kS;
    #pragma unroll
    for (int nd = 0; nd < 8; ++nd) {
        const int hd = nd * 8 + 2 * lc;
        Op[(size_t)hd * kS + q0]           = oacc[nd][0] * inv0;
        Op[(size_t)(hd + 1) * kS + q0]     = oacc[nd][1] * inv0;
        Op[(size_t)hd * kS + q0 + 8]       = oacc[nd][2] * inv1;
        Op[(size_t)(hd + 1) * kS + q0 + 8] = oacc[nd][3] * inv1;
    }
}

extern "C" void kernel_launch(void* const* d_in, const int* in_sizes, int n_in,
                              void* d_out, int out_size)
{
    (void)in_sizes; (void)n_in; (void)out_size;
    const float* x  = (const float*)d_in[0];
    const float* Wq = (const float*)d_in[2];
    const float* bq = (const float*)d_in[3];
    const float* Wk = (const float*)d_in[4];
    const float* bk = (const float*)d_in[5];
    const float* Wv = (const float*)d_in[6];
    const float* bv = (const float*)d_in[7];
    const float* Wo = (const float*)d_in[8];
    const float* bo = (const float*)d_in[9];
    float* out = (float*)d_out;

    void *qp, *kp, *vp, *op;
    cudaGetSymbolAddress(&qp, g_Q);
    cudaGetSymbolAddress(&kp, g_K);
    cudaGetSymbolAddress(&vp, g_V);
    cudaGetSymbolAddress(&op, g_O);

    cudaFuncSetAttribute(attn_mma, cudaFuncAttributeMaxDynamicSharedMemorySize, SMEM_ATTN);

    gemm_proj<<<dim3(kD / 64, (kB * kS) / 64), 256>>>(x, Wq, bq, (float*)qp, kD, kNH, kHD);
    gemm_proj<<<dim3((kGH * kHD) / 64, (kB * kS) / 64), 256>>>(x, Wk, bk, (float*)kp, kGH * kHD, kGH, kHD);
    gemm_proj<<<dim3((kGH * kHD) / 64, (kB * kS) / 64), 256>>>(x, Wv, bv, (float*)vp, kGH * kHD, kGH, kHD);

    attn_mma<<<dim3(kS / 128, kNH, kB), 256, SMEM_ATTN>>>();

    gemm_proj<<<dim3(kD / 64, (kB * kS) / 64), 256>>>((const float*)op, Wo, bo, out, kD, 1, kD);
}

// round 5
// speedup vs baseline: 2.5478x; 1.4500x over previous
#include <cuda_runtime.h>
#include <cuda_fp16.h>
#include <cstdint>

// GroupQuerySelfAttention: B=2, S=2048, D=768, NH=12, GH=4 (rep=3), HD=64
// MASK_FILL = -1e-9 => masked P entries == exp(-1e-9) == 1.0f; softmax needs
// no max subtraction. Attention: mma.sync (tf32 QK^T rna, fp16 PV).
// Projections: tf32 mma.sync GEMM, double-buffered.
// Buggy merge == attention out stored [B, NH, HD, S].

namespace {
constexpr int kB  = 2;
constexpr int kS  = 2048;
constexpr int kD  = 768;
constexpr int kNH = 12;
constexpr int kGH = 4;
constexpr int kHD = 64;
constexpr int kREP = 3;
constexpr float kScale = 0.125f;
}

__device__ float g_Q[(size_t)kB * kNH * kS * kHD];   // [b, h, s, hd]
__device__ float g_K[(size_t)kB * kGH * kS * kHD];   // [b, g, s, hd]
__device__ float g_V[(size_t)kB * kGH * kS * kHD];   // [b, g, s, hd]
__device__ float g_O[(size_t)kB * kNH * kHD * kS];   // [b, h, hd, q]

// ---------------------------------------------------------------------------
// mma.sync helpers (baseline PTX — compute_103-family safe)
// ---------------------------------------------------------------------------
__device__ __forceinline__ void mma_tf32(float* d, const uint32_t* a,
                                         uint32_t b0, uint32_t b1) {
    asm volatile(
        "mma.sync.aligned.m16n8k8.row.col.f32.tf32.tf32.f32 "
        "{%0,%1,%2,%3}, {%4,%5,%6,%7}, {%8,%9}, {%0,%1,%2,%3};"
        : "+f"(d[0]), "+f"(d[1]), "+f"(d[2]), "+f"(d[3])
        : "r"(a[0]), "r"(a[1]), "r"(a[2]), "r"(a[3]), "r"(b0), "r"(b1));
}
__device__ __forceinline__ void mma_f16(float* d, const uint32_t* a,
                                        uint32_t b0, uint32_t b1) {
    asm volatile(
        "mma.sync.aligned.m16n8k16.row.col.f32.f16.f16.f32 "
        "{%0,%1,%2,%3}, {%4,%5,%6,%7}, {%8,%9}, {%0,%1,%2,%3};"
        : "+f"(d[0]), "+f"(d[1]), "+f"(d[2]), "+f"(d[3])
        : "r"(a[0]), "r"(a[1]), "r"(a[2]), "r"(a[3]), "r"(b0), "r"(b1));
}
__device__ __forceinline__ uint32_t pack_f16(float lo, float hi) {
    uint32_t r;
    asm("cvt.rn.f16x2.f32 %0, %1, %2;" : "=r"(r) : "f"(hi), "f"(lo));
    return r;
}
__device__ __forceinline__ float rna_tf32(float f) {
    uint32_t r;
    asm("cvt.rna.tf32.f32 %0, %1;" : "=r"(r) : "f"(f));
    return __uint_as_float(r);
}

// ---------------------------------------------------------------------------
// tf32 tensor-core projection GEMM.
// C[4096 x N] = A[4096 x 768] @ W[768 x N] + bias, head-major output scatter.
// CTA tile 128m x 64n, 8 warps (warp = 16m x 64n). K-chunks of 32 (4 k-steps),
// double-buffered smem; LDG for chunk i+1 overlaps mma on chunk i.
// Smem: As[2][128][36] + Ws[2][64][36] (Ws stores W transposed [n][k]).
// ---------------------------------------------------------------------------
namespace {
constexpr int AST = 36;                         // padded strides (conflict-free)
constexpr int SMEM_GEMM = (2 * 128 * AST + 2 * 64 * AST) * 4;  // 55296 B
}

__global__ __launch_bounds__(256) void gemm_tf32(
    const float* __restrict__ A, const float* __restrict__ W,
    const float* __restrict__ bias, float* __restrict__ out,
    int N, int heads, int hd)
{
    extern __shared__ float sg[];
    float* As = sg;                       // [2][128][36]
    float* Ws = sg + 2 * 128 * AST;       // [2][64][36]

    const int tid = threadIdx.x;
    const int lane = tid & 31;
    const int w = tid >> 5;
    const int lr = lane >> 2;
    const int lc = lane & 3;
    const int rowBase = blockIdx.y * 128;
    const int colBase = blockIdx.x * 64;

    float acc[8][4];
    #pragma unroll
    for (int i = 0; i < 8; ++i)
        #pragma unroll
        for (int j = 0; j < 4; ++j) acc[i][j] = 0.f;

    float4 aL[4], wL[2];
    auto load_chunk = [&](int k0) {
        #pragma unroll
        for (int j = 0; j < 4; ++j) {
            const int fid = tid + 256 * j;
            const int r = fid >> 3, k4 = fid & 7;
            aL[j] = *reinterpret_cast<const float4*>(
                A + (size_t)(rowBase + r) * kD + k0 + k4 * 4);
        }
        #pragma unroll
        for (int j = 0; j < 2; ++j) {
            const int fid = tid + 256 * j;
            const int k = fid >> 4, n4 = fid & 15;
            wL[j] = *reinterpret_cast<const float4*>(
                W + (size_t)(k0 + k) * N + colBase + n4 * 4);
        }
    };
    auto store_chunk = [&](int buf) {
        float* Ab = As + buf * 128 * AST;
        float* Wb = Ws + buf * 64 * AST;
        #pragma unroll
        for (int j = 0; j < 4; ++j) {
            const int fid = tid + 256 * j;
            const int r = fid >> 3, k4 = fid & 7;
            float* d = Ab + r * AST + k4 * 4;
            d[0] = rna_tf32(aL[j].x); d[1] = rna_tf32(aL[j].y);
            d[2] = rna_tf32(aL[j].z); d[3] = rna_tf32(aL[j].w);
        }
        #pragma unroll
        for (int j = 0; j < 2; ++j) {
            const int fid = tid + 256 * j;
            const int k = fid >> 4, n4 = fid & 15;
            Wb[(n4 * 4 + 0) * AST + k] = rna_tf32(wL[j].x);
            Wb[(n4 * 4 + 1) * AST + k] = rna_tf32(wL[j].y);
            Wb[(n4 * 4 + 2) * AST + k] = rna_tf32(wL[j].z);
            Wb[(n4 * 4 + 3) * AST + k] = rna_tf32(wL[j].w);
        }
    };

    load_chunk(0);
    store_chunk(0);
    __syncthreads();

    const int nch = kD / 32;   // 24
    for (int ch = 0; ch < nch; ++ch) {
        if (ch + 1 < nch) load_chunk((ch + 1) * 32);

        const float* Ab = As + (ch & 1) * 128 * AST;
        const float* Wb = Ws + (ch & 1) * 64 * AST;
        const int r0 = w * 16 + lr;
        #pragma unroll
        for (int ks = 0; ks < 4; ++ks) {
            uint32_t a[4];
            a[0] = __float_as_uint(Ab[r0 * AST + ks * 8 + lc]);
            a[1] = __float_as_uint(Ab[(r0 + 8) * AST + ks * 8 + lc]);
            a[2] = __float_as_uint(Ab[r0 * AST + ks * 8 + lc + 4]);
            a[3] = __float_as_uint(Ab[(r0 + 8) * AST + ks * 8 + lc + 4]);
            #pragma unroll
            for (int nf = 0; nf < 8; ++nf) {
                const float* wrow = Wb + (nf * 8 + lr) * AST;
                const uint32_t b0 = __float_as_uint(wrow[ks * 8 + lc]);
                const uint32_t b1 = __float_as_uint(wrow[ks * 8 + lc + 4]);
                mma_tf32(acc[nf], a, b0, b1);
            }
        }

        if (ch + 1 < nch) store_chunk((ch + 1) & 1);
        __syncthreads();
    }

    // write out with head-major scatter
    const int r0 = rowBase + w * 16 + lr;
    #pragma unroll
    for (int half = 0; half < 2; ++half) {
        const int r = r0 + half * 8;
        const int bb = r / kS, s = r - bb * kS;
        #pragma unroll
        for (int nf = 0; nf < 8; ++nf) {
            const int c = colBase + nf * 8 + 2 * lc;
            const int h = c / hd, cc = c - h * hd;
            float* dst = out + ((size_t)(bb * heads + h) * kS + s) * hd + cc;
            dst[0] = acc[nf][half * 2 + 0] + bias[c];
            dst[1] = acc[nf][half * 2 + 1] + bias[c + 1];
        }
    }
}

// ---------------------------------------------------------------------------
// Tensor-core attention (unchanged from R4 — proven at 364 us / 2.8e-4)
// ---------------------------------------------------------------------------
namespace {
constexpr int QS_STRIDE = 68;
constexpr int VT_STRIDE = 72;
constexpr int SMEM_ATTN = 128 * 68 * 4 + 64 * 68 * 4 + 64 * 72 * 2;  // 61440
}

__global__ __launch_bounds__(256, 2) void attn_mma()
{
    extern __shared__ char smem[];
    float* Qs = reinterpret_cast<float*>(smem);                  // [128][68]
    float* Ks = Qs + 128 * QS_STRIDE;                            // [64][68]
    __half* Vt = reinterpret_cast<__half*>(Ks + 64 * QS_STRIDE); // [64][72]

    const int tid = threadIdx.x;
    const int lane = tid & 31;
    const int w = tid >> 5;
    const int qt = blockIdx.x, h = blockIdx.y, b = blockIdx.z;
    const int g = h / kREP;
    const int lr = lane >> 2;
    const int lc = lane & 3;

    const float* Qp = g_Q + ((size_t)(b * kNH + h) * kS + (size_t)qt * 128) * kHD;
    const float* Kp = g_K + (size_t)(b * kGH + g) * kS * kHD;
    const float* Vp = g_V + (size_t)(b * kGH + g) * kS * kHD;

    for (int i = tid; i < 128 * 16; i += 256) {
        const int r = i >> 4, c4 = (i & 15) * 4;
        float4 v = *reinterpret_cast<const float4*>(Qp + (size_t)r * kHD + c4);
        float* dst = Qs + r * QS_STRIDE + c4;
        dst[0] = rna_tf32(v.x); dst[1] = rna_tf32(v.y);
        dst[2] = rna_tf32(v.z); dst[3] = rna_tf32(v.w);
    }
    __syncthreads();

    uint32_t qa[8][4];
    {
        const int r0 = w * 16 + lr;
        #pragma unroll
        for (int ks = 0; ks < 8; ++ks) {
            qa[ks][0] = __float_as_uint(Qs[r0 * QS_STRIDE + ks * 8 + lc]);
            qa[ks][1] = __float_as_uint(Qs[(r0 + 8) * QS_STRIDE + ks * 8 + lc]);
            qa[ks][2] = __float_as_uint(Qs[r0 * QS_STRIDE + ks * 8 + lc + 4]);
            qa[ks][3] = __float_as_uint(Qs[(r0 + 8) * QS_STRIDE + ks * 8 + lc + 4]);
        }
    }

    float oacc[8][4];
    #pragma unroll
    for (int i = 0; i < 8; ++i)
        #pragma unroll
        for (int j = 0; j < 4; ++j) oacc[i][j] = 0.f;
    float lsum0 = 0.f, lsum1 = 0.f;
    const int q0 = qt * 128 + w * 16 + lr;

    for (int kt = 0; kt < kS / 64; ++kt) {
        __syncthreads();
        const float* Kt  = Kp + (size_t)kt * 64 * kHD;
        const float* Vtg = Vp + (size_t)kt * 64 * kHD;
        for (int i = tid; i < 64 * 16; i += 256) {
            const int r = i >> 4, c4 = (i & 15) * 4;
            float4 v = *reinterpret_cast<const float4*>(Kt + (size_t)r * kHD + c4);
            float* dst = Ks + r * QS_STRIDE + c4;
            dst[0] = rna_tf32(v.x); dst[1] = rna_tf32(v.y);
            dst[2] = rna_tf32(v.z); dst[3] = rna_tf32(v.w);
        }
        for (int i = tid; i < 64 * 16; i += 256) {
            const int r = i >> 4, c4 = (i & 15) * 4;
            float4 v = *reinterpret_cast<const float4*>(Vtg + (size_t)r * kHD + c4);
            Vt[(c4 + 0) * VT_STRIDE + r] = __float2half_rn(v.x);
            Vt[(c4 + 1) * VT_STRIDE + r] = __float2half_rn(v.y);
            Vt[(c4 + 2) * VT_STRIDE + r] = __float2half_rn(v.z);
            Vt[(c4 + 3) * VT_STRIDE + r] = __float2half_rn(v.w);
        }
        __syncthreads();

        #pragma unroll
        for (int sub = 0; sub < 2; ++sub) {
            float sacc[4][4];
            #pragma unroll
            for (int i = 0; i < 4; ++i)
                #pragma unroll
                for (int j = 0; j < 4; ++j) sacc[i][j] = 0.f;

            #pragma unroll
            for (int nf = 0; nf < 4; ++nf) {
                const int key = sub * 32 + nf * 8 + lr;
                const float* krow = Ks + key * QS_STRIDE;
                #pragma unroll
                for (int ks = 0; ks < 8; ++ks) {
                    const uint32_t b0 = __float_as_uint(krow[ks * 8 + lc]);
                    const uint32_t b1 = __float_as_uint(krow[ks * 8 + lc + 4]);
                    mma_tf32(sacc[nf], qa[ks], b0, b1);
                }
            }

            uint32_t pa[2][4];
            #pragma unroll
            for (int nf = 0; nf < 4; ++nf) {
                const int colb = kt * 64 + sub * 32 + nf * 8 + 2 * lc;
                const float p0 = (colb     <= q0)     ? __expf(sacc[nf][0] * kScale) : 1.0f;
                const float p1 = (colb + 1 <= q0)     ? __expf(sacc[nf][1] * kScale) : 1.0f;
                const float p2 = (colb     <= q0 + 8) ? __expf(sacc[nf][2] * kScale) : 1.0f;
                const float p3 = (colb + 1 <= q0 + 8) ? __expf(sacc[nf][3] * kScale) : 1.0f;
                lsum0 += p0 + p1;
                lsum1 += p2 + p3;
                const int kk = nf >> 1;
                if ((nf & 1) == 0) {
                    pa[kk][0] = pack_f16(p0, p1);
                    pa[kk][1] = pack_f16(p2, p3);
                } else {
                    pa[kk][2] = pack_f16(p0, p1);
                    pa[kk][3] = pack_f16(p2, p3);
                }
            }

            #pragma unroll
            for (int nd = 0; nd < 8; ++nd) {
                const __half* vrow = Vt + (nd * 8 + lr) * VT_STRIDE + sub * 32;
                #pragma unroll
                for (int kk = 0; kk < 2; ++kk) {
                    const uint32_t b0 = *reinterpret_cast<const uint32_t*>(vrow + kk * 16 + 2 * lc);
                    const uint32_t b1 = *reinterpret_cast<const uint32_t*>(vrow + kk * 16 + 2 * lc + 8);
                    mma_f16(oacc[nd], pa[kk], b0, b1);
                }
            }
        }
    }

    lsum0 += __shfl_xor_sync(0xffffffffu, lsum0, 1);
    lsum0 += __shfl_xor_sync(0xffffffffu, lsum0, 2);
    lsum1 += __shfl_xor_sync(0xffffffffu, lsum1, 1);
    lsum1 += __shfl_xor_sync(0xffffffffu, lsum1, 2);
    const float inv0 = 1.f / lsum0;
    const float inv1 = 1.f / lsum1;

    float* Op = g_O + (size_t)(b * kNH + h) * kHD * kS;
    #pragma unroll
    for (int nd = 0; nd < 8; ++nd) {
        const int hd = nd * 8 + 2 * lc;
        Op[(size_t)hd * kS + q0]           = oacc[nd][0] * inv0;
        Op[(size_t)(hd + 1) * kS + q0]     = oacc[nd][1] * inv0;
        Op[(size_t)hd * kS + q0 + 8]       = oacc[nd][2] * inv1;
        Op[(size_t)(hd + 1) * kS + q0 + 8] = oacc[nd][3] * inv1;
    }
}

extern "C" void kernel_launch(void* const* d_in, const int* in_sizes, int n_in,
                              void* d_out, int out_size)
{
    (void)in_sizes; (void)n_in; (void)out_size;
    const float* x  = (const float*)d_in[0];
    const float* Wq = (const float*)d_in[2];
    const float* bq = (const float*)d_in[3];
    const float* Wk = (const float*)d_in[4];
    const float* bk = (const float*)d_in[5];
    const float* Wv = (const float*)d_in[6];
    const float* bv = (const float*)d_in[7];
    const float* Wo = (const float*)d_in[8];
    const float* bo = (const float*)d_in[9];
    float* out = (float*)d_out;

    void *qp, *kp, *vp, *op;
    cudaGetSymbolAddress(&qp, g_Q);
    cudaGetSymbolAddress(&kp, g_K);
    cudaGetSymbolAddress(&vp, g_V);
    cudaGetSymbolAddress(&op, g_O);

    cudaFuncSetAttribute(attn_mma, cudaFuncAttributeMaxDynamicSharedMemorySize, SMEM_ATTN);
    cudaFuncSetAttribute(gemm_tf32, cudaFuncAttributeMaxDynamicSharedMemorySize, SMEM_GEMM);

    gemm_tf32<<<dim3(kD / 64, (kB * kS) / 128), 256, SMEM_GEMM>>>(x, Wq, bq, (float*)qp, kD, kNH, kHD);
    gemm_tf32<<<dim3((kGH * kHD) / 64, (kB * kS) / 128), 256, SMEM_GEMM>>>(x, Wk, bk, (float*)kp, kGH * kHD, kGH, kHD);
    gemm_tf32<<<dim3((kGH * kHD) / 64, (kB * kS) / 128), 256, SMEM_GEMM>>>(x, Wv, bv, (float*)vp, kGH * kHD, kGH, kHD);

    attn_mma<<<dim3(kS / 128, kNH, kB), 256, SMEM_ATTN>>>();

    gemm_tf32<<<dim3(kD / 64, (kB * kS) / 128), 256, SMEM_GEMM>>>((const float*)op, Wo, bo, out, kD, 1, kD);
}

// round 6
// speedup vs baseline: 3.2110x; 1.2603x over previous
#include <cuda_runtime.h>
#include <cuda_fp16.h>
#include <cstdint>

// GroupQuerySelfAttention: B=2, S=2048, D=768, NH=12, GH=4 (rep=3), HD=64
// MASK_FILL = -1e-9 => masked P entries == exp(-1e-9) == 1.0f; softmax needs
// no max subtraction. Attention: fp16 mma.sync for BOTH QK^T and PV (fp16 and
// tf32 have identical 10-bit mantissas), 3-stage cp.async pipeline.
// Projections: tf32 mma.sync GEMM (proven). Buggy merge == out as [B,NH,HD,S].

namespace {
constexpr int kB  = 2;
constexpr int kS  = 2048;
constexpr int kD  = 768;
constexpr int kNH = 12;
constexpr int kGH = 4;
constexpr int kHD = 64;
constexpr int kREP = 3;
constexpr float kScale = 0.125f;
}

__device__ float g_Q[(size_t)kB * kNH * kS * kHD];   // [b, h, s, hd]
__device__ float g_K[(size_t)kB * kGH * kS * kHD];   // [b, g, s, hd]
__device__ float g_V[(size_t)kB * kGH * kS * kHD];   // [b, g, s, hd]
__device__ float g_O[(size_t)kB * kNH * kHD * kS];   // [b, h, hd, q]

// ---------------------------------------------------------------------------
// mma.sync helpers (baseline PTX — compute_103-family safe)
// ---------------------------------------------------------------------------
__device__ __forceinline__ void mma_tf32(float* d, const uint32_t* a,
                                         uint32_t b0, uint32_t b1) {
    asm volatile(
        "mma.sync.aligned.m16n8k8.row.col.f32.tf32.tf32.f32 "
        "{%0,%1,%2,%3}, {%4,%5,%6,%7}, {%8,%9}, {%0,%1,%2,%3};"
        : "+f"(d[0]), "+f"(d[1]), "+f"(d[2]), "+f"(d[3])
        : "r"(a[0]), "r"(a[1]), "r"(a[2]), "r"(a[3]), "r"(b0), "r"(b1));
}
__device__ __forceinline__ void mma_f16(float* d, const uint32_t* a,
                                        uint32_t b0, uint32_t b1) {
    asm volatile(
        "mma.sync.aligned.m16n8k16.row.col.f32.f16.f16.f32 "
        "{%0,%1,%2,%3}, {%4,%5,%6,%7}, {%8,%9}, {%0,%1,%2,%3};"
        : "+f"(d[0]), "+f"(d[1]), "+f"(d[2]), "+f"(d[3])
        : "r"(a[0]), "r"(a[1]), "r"(a[2]), "r"(a[3]), "r"(b0), "r"(b1));
}
__device__ __forceinline__ uint32_t pack_f16(float lo, float hi) {
    uint32_t r;
    asm("cvt.rn.f16x2.f32 %0, %1, %2;" : "=r"(r) : "f"(hi), "f"(lo));
    return r;
}
__device__ __forceinline__ float rna_tf32(float f) {
    uint32_t r;
    asm("cvt.rna.tf32.f32 %0, %1;" : "=r"(r) : "f"(f));
    return __uint_as_float(r);
}
__device__ __forceinline__ uint32_t smem_u32(const void* p) {
    uint32_t a;
    asm("{ .reg .u64 t; cvta.to.shared.u64 t, %1; cvt.u32.u64 %0, t; }"
        : "=r"(a) : "l"(p));
    return a;
}
__device__ __forceinline__ void cp16(uint32_t dst, const void* src) {
    asm volatile("cp.async.cg.shared.global [%0], [%1], 16;"
                 :: "r"(dst), "l"(src) : "memory");
}
__device__ __forceinline__ void cp_commit() {
    asm volatile("cp.async.commit_group;" ::: "memory");
}
__device__ __forceinline__ void cp_wait1() {
    asm volatile("cp.async.wait_group 1;" ::: "memory");
}

// ---------------------------------------------------------------------------
// tf32 tensor-core projection GEMM (unchanged — proven in R5)
// ---------------------------------------------------------------------------
namespace {
constexpr int AST = 36;
constexpr int SMEM_GEMM = (2 * 128 * AST + 2 * 64 * AST) * 4;  // 55296 B
}

__global__ __launch_bounds__(256) void gemm_tf32(
    const float* __restrict__ A, const float* __restrict__ W,
    const float* __restrict__ bias, float* __restrict__ out,
    int N, int heads, int hd)
{
    extern __shared__ float sg[];
    float* As = sg;
    float* Ws = sg + 2 * 128 * AST;

    const int tid = threadIdx.x;
    const int lane = tid & 31;
    const int w = tid >> 5;
    const int lr = lane >> 2;
    const int lc = lane & 3;
    const int rowBase = blockIdx.y * 128;
    const int colBase = blockIdx.x * 64;

    float acc[8][4];
    #pragma unroll
    for (int i = 0; i < 8; ++i)
        #pragma unroll
        for (int j = 0; j < 4; ++j) acc[i][j] = 0.f;

    float4 aL[4], wL[2];
    auto load_chunk = [&](int k0) {
        #pragma unroll
        for (int j = 0; j < 4; ++j) {
            const int fid = tid + 256 * j;
            const int r = fid >> 3, k4 = fid & 7;
            aL[j] = *reinterpret_cast<const float4*>(
                A + (size_t)(rowBase + r) * kD + k0 + k4 * 4);
        }
        #pragma unroll
        for (int j = 0; j < 2; ++j) {
            const int fid = tid + 256 * j;
            const int k = fid >> 4, n4 = fid & 15;
            wL[j] = *reinterpret_cast<const float4*>(
                W + (size_t)(k0 + k) * N + colBase + n4 * 4);
        }
    };
    auto store_chunk = [&](int buf) {
        float* Ab = As + buf * 128 * AST;
        float* Wb = Ws + buf * 64 * AST;
        #pragma unroll
        for (int j = 0; j < 4; ++j) {
            const int fid = tid + 256 * j;
            const int r = fid >> 3, k4 = fid & 7;
            float* d = Ab + r * AST + k4 * 4;
            d[0] = rna_tf32(aL[j].x); d[1] = rna_tf32(aL[j].y);
            d[2] = rna_tf32(aL[j].z); d[3] = rna_tf32(aL[j].w);
        }
        #pragma unroll
        for (int j = 0; j < 2; ++j) {
            const int fid = tid + 256 * j;
            const int k = fid >> 4, n4 = fid & 15;
            Wb[(n4 * 4 + 0) * AST + k] = rna_tf32(wL[j].x);
            Wb[(n4 * 4 + 1) * AST + k] = rna_tf32(wL[j].y);
            Wb[(n4 * 4 + 2) * AST + k] = rna_tf32(wL[j].z);
            Wb[(n4 * 4 + 3) * AST + k] = rna_tf32(wL[j].w);
        }
    };

    load_chunk(0);
    store_chunk(0);
    __syncthreads();

    const int nch = kD / 32;   // 24
    for (int ch = 0; ch < nch; ++ch) {
        if (ch + 1 < nch) load_chunk((ch + 1) * 32);

        const float* Ab = As + (ch & 1) * 128 * AST;
        const float* Wb = Ws + (ch & 1) * 64 * AST;
        const int r0 = w * 16 + lr;
        #pragma unroll
        for (int ks = 0; ks < 4; ++ks) {
            uint32_t a[4];
            a[0] = __float_as_uint(Ab[r0 * AST + ks * 8 + lc]);
            a[1] = __float_as_uint(Ab[(r0 + 8) * AST + ks * 8 + lc]);
            a[2] = __float_as_uint(Ab[r0 * AST + ks * 8 + lc + 4]);
            a[3] = __float_as_uint(Ab[(r0 + 8) * AST + ks * 8 + lc + 4]);
            #pragma unroll
            for (int nf = 0; nf < 8; ++nf) {
                const float* wrow = Wb + (nf * 8 + lr) * AST;
                const uint32_t b0 = __float_as_uint(wrow[ks * 8 + lc]);
                const uint32_t b1 = __float_as_uint(wrow[ks * 8 + lc + 4]);
                mma_tf32(acc[nf], a, b0, b1);
            }
        }

        if (ch + 1 < nch) store_chunk((ch + 1) & 1);
        __syncthreads();
    }

    const int r0 = rowBase + w * 16 + lr;
    #pragma unroll
    for (int half = 0; half < 2; ++half) {
        const int r = r0 + half * 8;
        const int bb = r / kS, s = r - bb * kS;
        #pragma unroll
        for (int nf = 0; nf < 8; ++nf) {
            const int c = colBase + nf * 8 + 2 * lc;
            const int h = c / hd, cc = c - h * hd;
            float* dst = out + ((size_t)(bb * heads + h) * kS + s) * hd + cc;
            dst[0] = acc[nf][half * 2 + 0] + bias[c];
            dst[1] = acc[nf][half * 2 + 1] + bias[c + 1];
        }
    }
}

// ---------------------------------------------------------------------------
// Pipelined fp16 attention. CTA = 128 q of one (b,h), 8 warps, warp = 16 q.
// 3-stage cp.async pipeline over 64-key tiles (raw f32 K,V in smem; convert
// to f16 at fragment load). Q region overlaid on stage 2 (freed post-hoist).
// Per iteration: cp.wait_group(1) -> barrier -> compute -> issue stage kt+2.
// Smem: 3 stages x (K 64x68 f32 + V 64x68 f32) = 104448 B, 2 CTAs/SM.
// ---------------------------------------------------------------------------
namespace {
constexpr int KVST = 68;                       // f32 words per tile row
constexpr int TILE_B = 64 * KVST * 4;          // 17408 per K or V tile
constexpr int STAGE_B = 2 * TILE_B;            // 34816 per stage
constexpr int SMEM_ATTN = 3 * STAGE_B;         // 104448
constexpr int NKT = kS / 64;                   // 32 key tiles
}

__global__ __launch_bounds__(256, 2) void attn_mma()
{
    extern __shared__ char smem[];
    const uint32_t sb = smem_u32(smem);

    const int tid = threadIdx.x;
    const int lane = tid & 31;
    const int w = tid >> 5;
    const int qt = blockIdx.x, h = blockIdx.y, b = blockIdx.z;
    const int g = h / kREP;
    const int lr = lane >> 2;
    const int lc = lane & 3;

    const float* Qp = g_Q + ((size_t)(b * kNH + h) * kS + (size_t)qt * 128) * kHD;
    const float* Kp = g_K + (size_t)(b * kGH + g) * kS * kHD;
    const float* Vp = g_V + (size_t)(b * kGH + g) * kS * kHD;

    // staging decomposition: 4 float4 chunks each for K and V per thread
    const int sr  = tid >> 2;             // base row group
    const int sc4 = (tid & 3) * 4;        // (with +256*j: r = c>>4, c4=(c&15)*4)
    (void)sr; (void)sc4;

    auto stage_tile = [&](int kt, int s) {
        const float* Kt = Kp + (size_t)kt * 64 * kHD;
        const float* Vt = Vp + (size_t)kt * 64 * kHD;
        const uint32_t kb = sb + s * STAGE_B;
        const uint32_t vb = kb + TILE_B;
        #pragma unroll
        for (int j = 0; j < 4; ++j) {
            const int c = tid + 256 * j;
            const int r = c >> 4, c4 = (c & 15) * 4;
            const uint32_t off = (uint32_t)(r * KVST + c4) * 4;
            cp16(kb + off, Kt + r * kHD + c4);
            cp16(vb + off, Vt + r * kHD + c4);
        }
        cp_commit();
    };

    stage_tile(0, 0);
    stage_tile(1, 1);

    // stage Q [128 x 64] into stage-2 region (freed after fragment hoist)
    float* Qs = reinterpret_cast<float*>(smem + 2 * STAGE_B);   // [128][68]
    #pragma unroll
    for (int j = 0; j < 8; ++j) {
        const int c = tid + 256 * j;
        const int r = c >> 4, c4 = (c & 15) * 4;
        float4 v = *reinterpret_cast<const float4*>(Qp + (size_t)r * kHD + c4);
        float* dst = Qs + r * KVST + c4;
        dst[0] = v.x; dst[1] = v.y; dst[2] = v.z; dst[3] = v.w;
    }
    __syncthreads();

    // hoist Q fragments as f16 (m16n8k16 A): qa[ks][0..3]
    uint32_t qa[4][4];
    {
        const int r0 = w * 16 + lr;
        #pragma unroll
        for (int ks = 0; ks < 4; ++ks) {
            const int cb = ks * 16 + 2 * lc;
            float2 t0 = *reinterpret_cast<const float2*>(Qs + r0 * KVST + cb);
            float2 t1 = *reinterpret_cast<const float2*>(Qs + (r0 + 8) * KVST + cb);
            float2 t2 = *reinterpret_cast<const float2*>(Qs + r0 * KVST + cb + 8);
            float2 t3 = *reinterpret_cast<const float2*>(Qs + (r0 + 8) * KVST + cb + 8);
            qa[ks][0] = pack_f16(t0.x, t0.y);
            qa[ks][1] = pack_f16(t1.x, t1.y);
            qa[ks][2] = pack_f16(t2.x, t2.y);
            qa[ks][3] = pack_f16(t3.x, t3.y);
        }
    }

    float oacc[8][4];
    #pragma unroll
    for (int i = 0; i < 8; ++i)
        #pragma unroll
        for (int j = 0; j < 4; ++j) oacc[i][j] = 0.f;
    float lsum0 = 0.f, lsum1 = 0.f;
    const int q0 = qt * 128 + w * 16 + lr;

    int buf = 0;
    for (int kt = 0; kt < NKT; ++kt) {
        cp_wait1();
        __syncthreads();   // stage kt fully resident; all warps done with kt-1

        const float* Kb = reinterpret_cast<const float*>(smem + buf * STAGE_B);
        const float* Vb = Kb + 64 * KVST;

        #pragma unroll
        for (int sub = 0; sub < 2; ++sub) {
            // S (16 x 32) = Q @ K^T, fp16 (fp32 accum)
            float sacc[4][4];
            #pragma unroll
            for (int i = 0; i < 4; ++i)
                #pragma unroll
                for (int j = 0; j < 4; ++j) sacc[i][j] = 0.f;

            #pragma unroll
            for (int nf = 0; nf < 4; ++nf) {
                const float* krow = Kb + (sub * 32 + nf * 8 + lr) * KVST;
                #pragma unroll
                for (int ks = 0; ks < 4; ++ks) {
                    float2 u0 = *reinterpret_cast<const float2*>(krow + ks * 16 + 2 * lc);
                    float2 u1 = *reinterpret_cast<const float2*>(krow + ks * 16 + 2 * lc + 8);
                    mma_f16(sacc[nf], qa[ks], pack_f16(u0.x, u0.y), pack_f16(u1.x, u1.y));
                }
            }

            // softmax (exact: masked p == 1.0f) + repack to fp16 PV A-frags
            uint32_t pa[2][4];
            #pragma unroll
            for (int nf = 0; nf < 4; ++nf) {
                const int colb = kt * 64 + sub * 32 + nf * 8 + 2 * lc;
                const float p0 = (colb     <= q0)     ? __expf(sacc[nf][0] * kScale) : 1.0f;
                const float p1 = (colb + 1 <= q0)     ? __expf(sacc[nf][1] * kScale) : 1.0f;
                const float p2 = (colb     <= q0 + 8) ? __expf(sacc[nf][2] * kScale) : 1.0f;
                const float p3 = (colb + 1 <= q0 + 8) ? __expf(sacc[nf][3] * kScale) : 1.0f;
                lsum0 += p0 + p1;
                lsum1 += p2 + p3;
                const int kk = nf >> 1;
                if ((nf & 1) == 0) {
                    pa[kk][0] = pack_f16(p0, p1);
                    pa[kk][1] = pack_f16(p2, p3);
                } else {
                    pa[kk][2] = pack_f16(p0, p1);
                    pa[kk][3] = pack_f16(p2, p3);
                }
            }

            // O (16 x 64) += P @ V, fp16 (V converted at load from raw f32)
            #pragma unroll
            for (int nd = 0; nd < 8; ++nd) {
                const float* vcol = Vb + nd * 8 + lr;
                #pragma unroll
                for (int kk = 0; kk < 2; ++kk) {
                    const int k0 = (sub * 32 + kk * 16 + 2 * lc) * KVST;
                    const uint32_t b0 = pack_f16(vcol[k0], vcol[k0 + KVST]);
                    const uint32_t b1 = pack_f16(vcol[k0 + 8 * KVST], vcol[k0 + 9 * KVST]);
                    mma_f16(oacc[nd], pa[kk], b0, b1);
                }
            }
        }

        // issue stage kt+2 into the buffer freed by iteration kt-1
        if (kt + 2 < NKT) {
            stage_tile(kt + 2, (buf + 2) % 3);
        } else {
            cp_commit();   // keep group count uniform
        }
        buf = (buf + 1) % 3;
    }

    lsum0 += __shfl_xor_sync(0xffffffffu, lsum0, 1);
    lsum0 += __shfl_xor_sync(0xffffffffu, lsum0, 2);
    lsum1 += __shfl_xor_sync(0xffffffffu, lsum1, 1);
    lsum1 += __shfl_xor_sync(0xffffffffu, lsum1, 2);
    const float inv0 = 1.f / lsum0;
    const float inv1 = 1.f / lsum1;

    // write O transposed: g_O[b, h, hd, q]
    float* Op = g_O + (size_t)(b * kNH + h) * kHD * kS;
    #pragma unroll
    for (int nd = 0; nd < 8; ++nd) {
        const int hd = nd * 8 + 2 * lc;
        Op[(size_t)hd * kS + q0]           = oacc[nd][0] * inv0;
        Op[(size_t)(hd + 1) * kS + q0]     = oacc[nd][1] * inv0;
        Op[(size_t)hd * kS + q0 + 8]       = oacc[nd][2] * inv1;
        Op[(size_t)(hd + 1) * kS + q0 + 8] = oacc[nd][3] * inv1;
    }
}

extern "C" void kernel_launch(void* const* d_in, const int* in_sizes, int n_in,
                              void* d_out, int out_size)
{
    (void)in_sizes; (void)n_in; (void)out_size;
    const float* x  = (const float*)d_in[0];
    const float* Wq = (const float*)d_in[2];
    const float* bq = (const float*)d_in[3];
    const float* Wk = (const float*)d_in[4];
    const float* bk = (const float*)d_in[5];
    const float* Wv = (const float*)d_in[6];
    const float* bv = (const float*)d_in[7];
    const float* Wo = (const float*)d_in[8];
    const float* bo = (const float*)d_in[9];
    float* out = (float*)d_out;

    void *qp, *kp, *vp, *op;
    cudaGetSymbolAddress(&qp, g_Q);
    cudaGetSymbolAddress(&kp, g_K);
    cudaGetSymbolAddress(&vp, g_V);
    cudaGetSymbolAddress(&op, g_O);

    cudaFuncSetAttribute(attn_mma, cudaFuncAttributeMaxDynamicSharedMemorySize, SMEM_ATTN);
    cudaFuncSetAttribute(gemm_tf32, cudaFuncAttributeMaxDynamicSharedMemorySize, SMEM_GEMM);

    gemm_tf32<<<dim3(kD / 64, (kB * kS) / 128), 256, SMEM_GEMM>>>(x, Wq, bq, (float*)qp, kD, kNH, kHD);
    gemm_tf32<<<dim3((kGH * kHD) / 64, (kB * kS) / 128), 256, SMEM_GEMM>>>(x, Wk, bk, (float*)kp, kGH * kHD, kGH, kHD);
    gemm_tf32<<<dim3((kGH * kHD) / 64, (kB * kS) / 128), 256, SMEM_GEMM>>>(x, Wv, bv, (float*)vp, kGH * kHD, kGH, kHD);

    attn_mma<<<dim3(kS / 128, kNH, kB), 256, SMEM_ATTN>>>();

    gemm_tf32<<<dim3(kD / 64, (kB * kS) / 128), 256, SMEM_GEMM>>>((const float*)op, Wo, bo, out, kD, 1, kD);
}

// round 7
// speedup vs baseline: 4.2115x; 1.3116x over previous
#include <cuda_runtime.h>
#include <cuda_fp16.h>
#include <cstdint>

// GroupQuerySelfAttention: B=2, S=2048, D=768, NH=12, GH=4 (rep=3), HD=64
// MASK_FILL = -1e-9 => masked P entries == exp(-1e-9) == 1.0f; exact softmax
// without max subtraction. Projections: tf32 mma GEMM, writing f16 Q/K and
// pre-transposed f16 V. Attention: all-fp16 mma with f16 smem operands,
// 3-stage cp.async pipeline. Buggy merge == attention out as [B,NH,HD,S].

namespace {
constexpr int kB  = 2;
constexpr int kS  = 2048;
constexpr int kD  = 768;
constexpr int kNH = 12;
constexpr int kGH = 4;
constexpr int kHD = 64;
constexpr int kREP = 3;
constexpr float kScale = 0.125f;
}

__device__ __half g_Qh[(size_t)kB * kNH * kS * kHD];  // [b, h, s, hd]
__device__ __half g_Kh[(size_t)kB * kGH * kS * kHD];  // [b, g, s, hd]
__device__ __half g_Vh[(size_t)kB * kGH * kHD * kS];  // [b, g, hd, s]  (transposed!)
__device__ float  g_O [(size_t)kB * kNH * kHD * kS];  // [b, h, hd, q]

// ---------------------------------------------------------------------------
// PTX helpers (baseline — compute_103-family safe)
// ---------------------------------------------------------------------------
__device__ __forceinline__ void mma_tf32(float* d, const uint32_t* a,
                                         uint32_t b0, uint32_t b1) {
    asm volatile(
        "mma.sync.aligned.m16n8k8.row.col.f32.tf32.tf32.f32 "
        "{%0,%1,%2,%3}, {%4,%5,%6,%7}, {%8,%9}, {%0,%1,%2,%3};"
        : "+f"(d[0]), "+f"(d[1]), "+f"(d[2]), "+f"(d[3])
        : "r"(a[0]), "r"(a[1]), "r"(a[2]), "r"(a[3]), "r"(b0), "r"(b1));
}
__device__ __forceinline__ void mma_f16(float* d, const uint32_t* a,
                                        uint32_t b0, uint32_t b1) {
    asm volatile(
        "mma.sync.aligned.m16n8k16.row.col.f32.f16.f16.f32 "
        "{%0,%1,%2,%3}, {%4,%5,%6,%7}, {%8,%9}, {%0,%1,%2,%3};"
        : "+f"(d[0]), "+f"(d[1]), "+f"(d[2]), "+f"(d[3])
        : "r"(a[0]), "r"(a[1]), "r"(a[2]), "r"(a[3]), "r"(b0), "r"(b1));
}
__device__ __forceinline__ uint32_t pack_f16(float lo, float hi) {
    uint32_t r;
    asm("cvt.rn.f16x2.f32 %0, %1, %2;" : "=r"(r) : "f"(hi), "f"(lo));
    return r;
}
__device__ __forceinline__ float rna_tf32(float f) {
    uint32_t r;
    asm("cvt.rna.tf32.f32 %0, %1;" : "=r"(r) : "f"(f));
    return __uint_as_float(r);
}
__device__ __forceinline__ uint32_t smem_u32(const void* p) {
    uint32_t a;
    asm("{ .reg .u64 t; cvta.to.shared.u64 t, %1; cvt.u32.u64 %0, t; }"
        : "=r"(a) : "l"(p));
    return a;
}
__device__ __forceinline__ void cp16(uint32_t dst, const void* src) {
    asm volatile("cp.async.cg.shared.global [%0], [%1], 16;"
                 :: "r"(dst), "l"(src) : "memory");
}
__device__ __forceinline__ void cp_commit() {
    asm volatile("cp.async.commit_group;" ::: "memory");
}
__device__ __forceinline__ void cp_wait1() {
    asm volatile("cp.async.wait_group 1;" ::: "memory");
}

// ---------------------------------------------------------------------------
// tf32 projection GEMM (structure proven in R5/R6). Epilogue modes:
//   MODE 0: f32, head-major scatter   (final out-proj)
//   MODE 1: f16, [b, heads, s, hd]    (Q, K)
//   MODE 2: f16, [b, heads, hd, s]    (V, pre-transposed for attention)
// ---------------------------------------------------------------------------
namespace {
constexpr int AST = 36;
constexpr int SMEM_GEMM = (2 * 128 * AST + 2 * 64 * AST) * 4;  // 55296 B
}

template <int MODE, typename OutT>
__global__ __launch_bounds__(256) void gemm_tf32(
    const float* __restrict__ A, const float* __restrict__ W,
    const float* __restrict__ bias, OutT* __restrict__ out,
    int N, int heads, int hd)
{
    extern __shared__ float sg[];
    float* As = sg;
    float* Ws = sg + 2 * 128 * AST;

    const int tid = threadIdx.x;
    const int lane = tid & 31;
    const int w = tid >> 5;
    const int lr = lane >> 2;
    const int lc = lane & 3;
    const int rowBase = blockIdx.y * 128;
    const int colBase = blockIdx.x * 64;

    float acc[8][4];
    #pragma unroll
    for (int i = 0; i < 8; ++i)
        #pragma unroll
        for (int j = 0; j < 4; ++j) acc[i][j] = 0.f;

    float4 aL[4], wL[2];
    auto load_chunk = [&](int k0) {
        #pragma unroll
        for (int j = 0; j < 4; ++j) {
            const int fid = tid + 256 * j;
            const int r = fid >> 3, k4 = fid & 7;
            aL[j] = *reinterpret_cast<const float4*>(
                A + (size_t)(rowBase + r) * kD + k0 + k4 * 4);
        }
        #pragma unroll
        for (int j = 0; j < 2; ++j) {
            const int fid = tid + 256 * j;
            const int k = fid >> 4, n4 = fid & 15;
            wL[j] = *reinterpret_cast<const float4*>(
                W + (size_t)(k0 + k) * N + colBase + n4 * 4);
        }
    };
    auto store_chunk = [&](int buf) {
        float* Ab = As + buf * 128 * AST;
        float* Wb = Ws + buf * 64 * AST;
        #pragma unroll
        for (int j = 0; j < 4; ++j) {
            const int fid = tid + 256 * j;
            const int r = fid >> 3, k4 = fid & 7;
            float* d = Ab + r * AST + k4 * 4;
            d[0] = rna_tf32(aL[j].x); d[1] = rna_tf32(aL[j].y);
            d[2] = rna_tf32(aL[j].z); d[3] = rna_tf32(aL[j].w);
        }
        #pragma unroll
        for (int j = 0; j < 2; ++j) {
            const int fid = tid + 256 * j;
            const int k = fid >> 4, n4 = fid & 15;
            Wb[(n4 * 4 + 0) * AST + k] = rna_tf32(wL[j].x);
            Wb[(n4 * 4 + 1) * AST + k] = rna_tf32(wL[j].y);
            Wb[(n4 * 4 + 2) * AST + k] = rna_tf32(wL[j].z);
            Wb[(n4 * 4 + 3) * AST + k] = rna_tf32(wL[j].w);
        }
    };

    load_chunk(0);
    store_chunk(0);
    __syncthreads();

    const int nch = kD / 32;   // 24
    for (int ch = 0; ch < nch; ++ch) {
        if (ch + 1 < nch) load_chunk((ch + 1) * 32);

        const float* Ab = As + (ch & 1) * 128 * AST;
        const float* Wb = Ws + (ch & 1) * 64 * AST;
        const int r0 = w * 16 + lr;
        #pragma unroll
        for (int ks = 0; ks < 4; ++ks) {
            uint32_t a[4];
            a[0] = __float_as_uint(Ab[r0 * AST + ks * 8 + lc]);
            a[1] = __float_as_uint(Ab[(r0 + 8) * AST + ks * 8 + lc]);
            a[2] = __float_as_uint(Ab[r0 * AST + ks * 8 + lc + 4]);
            a[3] = __float_as_uint(Ab[(r0 + 8) * AST + ks * 8 + lc + 4]);
            #pragma unroll
            for (int nf = 0; nf < 8; ++nf) {
                const float* wrow = Wb + (nf * 8 + lr) * AST;
                const uint32_t b0 = __float_as_uint(wrow[ks * 8 + lc]);
                const uint32_t b1 = __float_as_uint(wrow[ks * 8 + lc + 4]);
                mma_tf32(acc[nf], a, b0, b1);
            }
        }

        if (ch + 1 < nch) store_chunk((ch + 1) & 1);
        __syncthreads();
    }

    const int r0 = rowBase + w * 16 + lr;
    #pragma unroll
    for (int half = 0; half < 2; ++half) {
        const int r = r0 + half * 8;
        const int bb = r / kS, s = r - bb * kS;
        #pragma unroll
        for (int nf = 0; nf < 8; ++nf) {
            const int c = colBase + nf * 8 + 2 * lc;
            const int h = c / hd, cc = c - h * hd;
            const float v0 = acc[nf][half * 2 + 0] + bias[c];
            const float v1 = acc[nf][half * 2 + 1] + bias[c + 1];
            if constexpr (MODE == 0) {
                float* dst = (float*)out + ((size_t)(bb * heads + h) * kS + s) * hd + cc;
                dst[0] = v0; dst[1] = v1;
            } else if constexpr (MODE == 1) {
                __half* dst = (__half*)out + ((size_t)(bb * heads + h) * kS + s) * hd + cc;
                *reinterpret_cast<uint32_t*>(dst) = pack_f16(v0, v1);
            } else {
                __half* base = (__half*)out + (size_t)(bb * heads + h) * hd * kS;
                base[(size_t)cc * kS + s]       = __float2half_rn(v0);
                base[(size_t)(cc + 1) * kS + s] = __float2half_rn(v1);
            }
        }
    }
}

// ---------------------------------------------------------------------------
// Pipelined all-fp16 attention. CTA = 128 q of one (b,h), 8 warps, 16 q each.
// f16 K tile [64 keys][72] and f16 V^T tile [64 hd][72] per stage; every mma
// B-operand is a single conflict-free LDS.32 (bank = 4*lr+lc). 3-stage
// cp.async pipeline (16 KB/stage + pad). Q overlaid on stage 2 (f16).
// Smem: 3 * 2 * 64 * 144 = 55296 B.
// ---------------------------------------------------------------------------
namespace {
constexpr int KST2 = 72;                       // f16 units per smem row
constexpr int TILE_B = 64 * KST2 * 2;          // 9216 B per tile
constexpr int STAGE_B = 2 * TILE_B;            // 18432 B per stage
constexpr int SMEM_ATTN = 3 * STAGE_B;         // 55296 B
constexpr int NKT = kS / 64;                   // 32 key tiles
}

__global__ __launch_bounds__(256, 2) void attn_mma()
{
    extern __shared__ char smem[];
    const uint32_t sb = smem_u32(smem);

    const int tid = threadIdx.x;
    const int lane = tid & 31;
    const int w = tid >> 5;
    const int qt = blockIdx.x, h = blockIdx.y, b = blockIdx.z;
    const int g = h / kREP;
    const int lr = lane >> 2;
    const int lc = lane & 3;

    const __half* Qp = g_Qh + ((size_t)(b * kNH + h) * kS + (size_t)qt * 128) * kHD;
    const __half* Kp = g_Kh + (size_t)(b * kGH + g) * kS * kHD;
    const __half* Vp = g_Vh + (size_t)(b * kGH + g) * kHD * kS;   // [hd][s]

    auto stage_tile = [&](int kt, int s) {
        const __half* Kt = Kp + (size_t)kt * 64 * kHD;      // rows = keys
        const __half* Vt = Vp + (size_t)kt * 64;            // rows = hd, +kt*64 keys
        const uint32_t kb = sb + s * STAGE_B;
        const uint32_t vb = kb + TILE_B;
        #pragma unroll
        for (int j = 0; j < 2; ++j) {
            const int c = tid + 256 * j;                    // 0..511
            const int r = c >> 3, c8 = (c & 7) * 8;         // row, f16 col base
            const uint32_t off = (uint32_t)(r * KST2 + c8) * 2;
            cp16(kb + off, Kt + (size_t)r * kHD + c8);
            cp16(vb + off, Vt + (size_t)r * kS + c8);
        }
        cp_commit();
    };

    stage_tile(0, 0);
    stage_tile(1, 1);

    // stage Q [128 x 64] f16 into stage-2 region (freed after fragment hoist)
    __half* Qs = reinterpret_cast<__half*>(smem + 2 * STAGE_B);   // [128][72]
    #pragma unroll
    for (int j = 0; j < 4; ++j) {
        const int c = tid + 256 * j;                        // 0..1023
        const int r = c >> 3, c8 = (c & 7) * 8;
        uint4 v = *reinterpret_cast<const uint4*>(Qp + (size_t)r * kHD + c8);
        *reinterpret_cast<uint4*>(Qs + r * KST2 + c8) = v;
    }
    __syncthreads();

    // hoist Q fragments (m16n8k16 A): single LDS.32 each
    uint32_t qa[4][4];
    {
        const int r0 = w * 16 + lr;
        #pragma unroll
        for (int ks = 0; ks < 4; ++ks) {
            const int cb = ks * 16 + 2 * lc;
            qa[ks][0] = *reinterpret_cast<const uint32_t*>(Qs + r0 * KST2 + cb);
            qa[ks][1] = *reinterpret_cast<const uint32_t*>(Qs + (r0 + 8) * KST2 + cb);
            qa[ks][2] = *reinterpret_cast<const uint32_t*>(Qs + r0 * KST2 + cb + 8);
            qa[ks][3] = *reinterpret_cast<const uint32_t*>(Qs + (r0 + 8) * KST2 + cb + 8);
        }
    }

    float oacc[8][4];
    #pragma unroll
    for (int i = 0; i < 8; ++i)
        #pragma unroll
        for (int j = 0; j < 4; ++j) oacc[i][j] = 0.f;
    float lsum0 = 0.f, lsum1 = 0.f;
    const int q0 = qt * 128 + w * 16 + lr;

    int buf = 0;
    for (int kt = 0; kt < NKT; ++kt) {
        cp_wait1();
        __syncthreads();   // stage kt resident; all warps done with kt-1

        const __half* Kb = reinterpret_cast<const __half*>(smem + buf * STAGE_B);
        const __half* Vb = Kb + 64 * KST2;   // V^T tile [hd][key]

        #pragma unroll
        for (int sub = 0; sub < 2; ++sub) {
            // S (16 x 32) = Q @ K^T, fp16 (fp32 accum)
            float sacc[4][4];
            #pragma unroll
            for (int i = 0; i < 4; ++i)
                #pragma unroll
                for (int j = 0; j < 4; ++j) sacc[i][j] = 0.f;

            #pragma unroll
            for (int nf = 0; nf < 4; ++nf) {
                const __half* krow = Kb + (sub * 32 + nf * 8 + lr) * KST2;
                #pragma unroll
                for (int ks = 0; ks < 4; ++ks) {
                    const uint32_t b0 = *reinterpret_cast<const uint32_t*>(krow + ks * 16 + 2 * lc);
                    const uint32_t b1 = *reinterpret_cast<const uint32_t*>(krow + ks * 16 + 2 * lc + 8);
                    mma_f16(sacc[nf], qa[ks], b0, b1);
                }
            }

            // softmax (exact: masked p == 1.0f) + repack to fp16 PV A-frags
            uint32_t pa[2][4];
            #pragma unroll
            for (int nf = 0; nf < 4; ++nf) {
                const int colb = kt * 64 + sub * 32 + nf * 8 + 2 * lc;
                const float p0 = (colb     <= q0)     ? __expf(sacc[nf][0] * kScale) : 1.0f;
                const float p1 = (colb + 1 <= q0)     ? __expf(sacc[nf][1] * kScale) : 1.0f;
                const float p2 = (colb     <= q0 + 8) ? __expf(sacc[nf][2] * kScale) : 1.0f;
                const float p3 = (colb + 1 <= q0 + 8) ? __expf(sacc[nf][3] * kScale) : 1.0f;
                lsum0 += p0 + p1;
                lsum1 += p2 + p3;
                const int kk = nf >> 1;
                if ((nf & 1) == 0) {
                    pa[kk][0] = pack_f16(p0, p1);
                    pa[kk][1] = pack_f16(p2, p3);
                } else {
                    pa[kk][2] = pack_f16(p0, p1);
                    pa[kk][3] = pack_f16(p2, p3);
                }
            }

            // O (16 x 64) += P @ V: B-frags single LDS.32 from V^T tile
            #pragma unroll
            for (int nd = 0; nd < 8; ++nd) {
                const __half* vrow = Vb + (nd * 8 + lr) * KST2 + sub * 32;
                #pragma unroll
                for (int kk = 0; kk < 2; ++kk) {
                    const uint32_t b0 = *reinterpret_cast<const uint32_t*>(vrow + kk * 16 + 2 * lc);
                    const uint32_t b1 = *reinterpret_cast<const uint32_t*>(vrow + kk * 16 + 2 * lc + 8);
                    mma_f16(oacc[nd], pa[kk], b0, b1);
                }
            }
        }

        if (kt + 2 < NKT) {
            stage_tile(kt + 2, (buf + 2) % 3);
        } else {
            cp_commit();   // keep group count uniform
        }
        buf = (buf + 1) % 3;
    }

    lsum0 += __shfl_xor_sync(0xffffffffu, lsum0, 1);
    lsum0 += __shfl_xor_sync(0xffffffffu, lsum0, 2);
    lsum1 += __shfl_xor_sync(0xffffffffu, lsum1, 1);
    lsum1 += __shfl_xor_sync(0xffffffffu, lsum1, 2);
    const float inv0 = 1.f / lsum0;
    const float inv1 = 1.f / lsum1;

    // write O transposed: g_O[b, h, hd, q]
    float* Op = g_O + (size_t)(b * kNH + h) * kHD * kS;
    #pragma unroll
    for (int nd = 0; nd < 8; ++nd) {
        const int hd = nd * 8 + 2 * lc;
        Op[(size_t)hd * kS + q0]           = oacc[nd][0] * inv0;
        Op[(size_t)(hd + 1) * kS + q0]     = oacc[nd][1] * inv0;
        Op[(size_t)hd * kS + q0 + 8]       = oacc[nd][2] * inv1;
        Op[(size_t)(hd + 1) * kS + q0 + 8] = oacc[nd][3] * inv1;
    }
}

extern "C" void kernel_launch(void* const* d_in, const int* in_sizes, int n_in,
                              void* d_out, int out_size)
{
    (void)in_sizes; (void)n_in; (void)out_size;
    const float* x  = (const float*)d_in[0];
    const float* Wq = (const float*)d_in[2];
    const float* bq = (const float*)d_in[3];
    const float* Wk = (const float*)d_in[4];
    const float* bk = (const float*)d_in[5];
    const float* Wv = (const float*)d_in[6];
    const float* bv = (const float*)d_in[7];
    const float* Wo = (const float*)d_in[8];
    const float* bo = (const float*)d_in[9];
    float* out = (float*)d_out;

    void *qp, *kp, *vp, *op;
    cudaGetSymbolAddress(&qp, g_Qh);
    cudaGetSymbolAddress(&kp, g_Kh);
    cudaGetSymbolAddress(&vp, g_Vh);
    cudaGetSymbolAddress(&op, g_O);

    cudaFuncSetAttribute(attn_mma, cudaFuncAttributeMaxDynamicSharedMemorySize, SMEM_ATTN);
    cudaFuncSetAttribute(gemm_tf32<0, float>,  cudaFuncAttributeMaxDynamicSharedMemorySize, SMEM_GEMM);
    cudaFuncSetAttribute(gemm_tf32<1, __half>, cudaFuncAttributeMaxDynamicSharedMemorySize, SMEM_GEMM);
    cudaFuncSetAttribute(gemm_tf32<2, __half>, cudaFuncAttributeMaxDynamicSharedMemorySize, SMEM_GEMM);

    gemm_tf32<1, __half><<<dim3(kD / 64, (kB * kS) / 128), 256, SMEM_GEMM>>>(
        x, Wq, bq, (__half*)qp, kD, kNH, kHD);
    gemm_tf32<1, __half><<<dim3((kGH * kHD) / 64, (kB * kS) / 128), 256, SMEM_GEMM>>>(
        x, Wk, bk, (__half*)kp, kGH * kHD, kGH, kHD);
    gemm_tf32<2, __half><<<dim3((kGH * kHD) / 64, (kB * kS) / 128), 256, SMEM_GEMM>>>(
        x, Wv, bv, (__half*)vp, kGH * kHD, kGH, kHD);

    attn_mma<<<dim3(kS / 128, kNH, kB), 256, SMEM_ATTN>>>();

    gemm_tf32<0, float><<<dim3(kD / 64, (kB * kS) / 128), 256, SMEM_GEMM>>>(
        (const float*)op, Wo, bo, out, kD, 1, kD);
}